// round 1
// baseline (speedup 1.0000x reference)
#include <cuda_runtime.h>
#include <cuda_bf16.h>

// AbsDiff cost volume:
//   out[n, d, y, x] = |image1[n,0,y,x] - image2[n,0,y,x-d]|  if x-d >= 0 else 0
// Shapes: in [2,1,384,1248] fp32, out [2,128,384,1248] fp32.
// HBM-write-bound: ~491 MB of stores, ~8 MB of reads.
// One block per (n,y) row: right row staged in smem once, left row in registers,
// then 128 d-iterations of conflict-free LDS + coalesced STG.

#define W_DIM   1248
#define H_DIM   384
#define N_DIM   2
#define D_DIM   128
#define THREADS 416   // 13 warps; 416 * 3 = 1248 = W exactly

__global__ __launch_bounds__(THREADS, 2)
void absdiff_costvol_kernel(const float* __restrict__ left,
                            const float* __restrict__ right,
                            float* __restrict__ out)
{
    __shared__ float sr[W_DIM];

    const int nh = blockIdx.x;                 // n*H + y
    const int t  = threadIdx.x;

    const float* lrow = left  + (size_t)nh * W_DIM;
    const float* rrow = right + (size_t)nh * W_DIM;

    // Stage right row into shared memory (vectorized, coalesced).
    // W/4 = 312 float4 loads across 416 threads.
    if (t < W_DIM / 4) {
        reinterpret_cast<float4*>(sr)[t] =
            reinterpret_cast<const float4*>(rrow)[t];
    }

    // Left row cached in registers: x = t, t+416, t+832 (all < 1248).
    const float l0 = lrow[t];
    const float l1 = lrow[t + THREADS];
    const float l2 = lrow[t + 2 * THREADS];

    __syncthreads();

    const int n = nh / H_DIM;
    const int y = nh % H_DIM;
    // out[n, d, y, x] = out + ((n*D + d)*H + y)*W + x
    float* ob = out + ((size_t)n * D_DIM * H_DIM + y) * W_DIM;

    #pragma unroll 4
    for (int d = 0; d < D_DIM; ++d) {
        const int i0 = t - d;                     // may be negative
        const int i1 = i0 + THREADS;              // >= 416-127 = 289, always valid
        const int i2 = i1 + THREADS;              // always valid

        const float r0 = sr[i0 < 0 ? 0 : i0];     // clamped, predicated-safe
        const float r1 = sr[i1];
        const float r2 = sr[i2];

        const float v0 = (i0 >= 0) ? fabsf(l0 - r0) : 0.0f;
        const float v1 = fabsf(l1 - r1);
        const float v2 = fabsf(l2 - r2);

        float* o = ob + (size_t)d * (H_DIM * W_DIM);
        o[t]               = v0;
        o[t + THREADS]     = v1;
        o[t + 2 * THREADS] = v2;
    }
}

extern "C" void kernel_launch(void* const* d_in, const int* in_sizes, int n_in,
                              void* d_out, int out_size)
{
    const float* image1 = (const float*)d_in[0];  // left
    const float* image2 = (const float*)d_in[1];  // right (shifted source)
    float* out = (float*)d_out;

    (void)in_sizes; (void)n_in; (void)out_size;

    dim3 grid(N_DIM * H_DIM);   // 768 blocks
    dim3 block(THREADS);
    absdiff_costvol_kernel<<<grid, block>>>(image1, image2, out);
}

// round 2
// speedup vs baseline: 1.0791x; 1.0791x over previous
#include <cuda_runtime.h>
#include <cuda_bf16.h>

// AbsDiff cost volume:
//   out[n, d, y, x] = |image1[n,0,y,x] - image2[n,0,y,x-d]|  if x-d >= 0 else 0
// Shapes: in [2,1,384,1248] fp32, out [2,128,384,1248] fp32.
// HBM-write-bound: ~491 MB stores. R2: split d 16-ways per (n,y) row to kill
// wave quantization (grid 768 -> 12288, conc 296 -> 592 via occ=4) at the
// cost of re-reading the 5KB input rows 16x (L2-hit, negligible).

#define W_DIM    1248
#define H_DIM    384
#define N_DIM    2
#define D_DIM    128
#define THREADS  416   // 13 warps; 416 * 3 = 1248 = W exactly
#define D_SPLIT  16
#define D_CHUNK  (D_DIM / D_SPLIT)   // 8 d-values per block

__global__ __launch_bounds__(THREADS, 4)
void absdiff_costvol_kernel(const float* __restrict__ left,
                            const float* __restrict__ right,
                            float* __restrict__ out)
{
    __shared__ float sr[W_DIM];

    const int nh = blockIdx.x;                 // n*H + y   (768)
    const int d0 = blockIdx.y * D_CHUNK;       // d chunk base (16 chunks)
    const int t  = threadIdx.x;

    const float* lrow = left  + (size_t)nh * W_DIM;
    const float* rrow = right + (size_t)nh * W_DIM;

    // Stage right row into shared memory (vectorized, coalesced).
    if (t < W_DIM / 4) {
        reinterpret_cast<float4*>(sr)[t] =
            reinterpret_cast<const float4*>(rrow)[t];
    }

    // Left row cached in registers: x = t, t+416, t+832 (all < 1248).
    const float l0 = lrow[t];
    const float l1 = lrow[t + THREADS];
    const float l2 = lrow[t + 2 * THREADS];

    __syncthreads();

    const int n = nh / H_DIM;
    const int y = nh % H_DIM;
    // out[n, d, y, x] = out + ((n*D + d)*H + y)*W + x
    float* ob = out + ((size_t)(n * D_DIM + d0) * H_DIM + y) * W_DIM;

    #pragma unroll
    for (int k = 0; k < D_CHUNK; ++k) {
        const int d  = d0 + k;
        const int i0 = t - d;                     // may be negative
        const int i1 = i0 + THREADS;              // >= 416-127 = 289, valid
        const int i2 = i1 + THREADS;              // valid

        const float r0 = sr[i0 < 0 ? 0 : i0];
        const float r1 = sr[i1];
        const float r2 = sr[i2];

        const float v0 = (i0 >= 0) ? fabsf(l0 - r0) : 0.0f;
        const float v1 = fabsf(l1 - r1);
        const float v2 = fabsf(l2 - r2);

        float* o = ob + (size_t)k * (H_DIM * W_DIM);
        o[t]               = v0;
        o[t + THREADS]     = v1;
        o[t + 2 * THREADS] = v2;
    }
}

extern "C" void kernel_launch(void* const* d_in, const int* in_sizes, int n_in,
                              void* d_out, int out_size)
{
    const float* image1 = (const float*)d_in[0];  // left
    const float* image2 = (const float*)d_in[1];  // right (shifted source)
    float* out = (float*)d_out;

    (void)in_sizes; (void)n_in; (void)out_size;

    dim3 grid(N_DIM * H_DIM, D_SPLIT);   // 768 x 16 = 12288 blocks
    dim3 block(THREADS);
    absdiff_costvol_kernel<<<grid, block>>>(image1, image2, out);
}

// round 3
// speedup vs baseline: 1.2094x; 1.1208x over previous
#include <cuda_runtime.h>
#include <cuda_bf16.h>

// AbsDiff cost volume:
//   out[n, d, y, x] = |image1[n,0,y,x] - image2[n,0,y,x-d]|  if x-d >= 0 else 0
// in [2,1,384,1248] fp32, out [2,128,384,1248] fp32. HBM-write-bound (~491MB).
// R3: float4 layout. 320-thread blocks (312 active), occ 6 -> 60 warps/SM.
// smem right-row padded with 128 leading zeros; misaligned window resolved at
// compile time (d-chunk fully unrolled, (-d)&3 = (-k)&3 constant). One
// STG.128 (streaming hint) per thread per d.

#define W_DIM    1248
#define H_DIM    384
#define N_DIM    2
#define D_DIM    128
#define W4       (W_DIM / 4)          // 312
#define THREADS  320                  // 10 warps; threads >= W4
#define D_SPLIT  16
#define D_CHUNK  (D_DIM / D_SPLIT)    // 8, multiple of 4 (so d0 % 4 == 0)
#define PAD      128                  // leading zeros so x-d never underflows

__device__ __forceinline__ void stcs4(float4* p, float4 v) {
    asm volatile("st.global.cs.v4.f32 [%0], {%1,%2,%3,%4};"
                 :: "l"(p), "f"(v.x), "f"(v.y), "f"(v.z), "f"(v.w) : "memory");
}

__global__ __launch_bounds__(THREADS, 6)
void absdiff_costvol_kernel(const float* __restrict__ left,
                            const float* __restrict__ right,
                            float* __restrict__ out)
{
    __shared__ float4 sr4[(PAD + W_DIM) / 4];   // 1376 floats = 5.5 KB

    const int nh = blockIdx.x;                  // n*H + y   (768)
    const int d0 = blockIdx.y * D_CHUNK;        // multiple of 8
    const int t  = threadIdx.x;

    const float4* rrow4 = (const float4*)(right + (size_t)nh * W_DIM);
    const float4* lrow4 = (const float4*)(left  + (size_t)nh * W_DIM);

    // Stage: zeros in the pad, right row after it.
    if (t < PAD / 4)
        sr4[t] = make_float4(0.f, 0.f, 0.f, 0.f);
    float4 L = make_float4(0.f, 0.f, 0.f, 0.f);
    if (t < W4) {
        sr4[PAD / 4 + t] = rrow4[t];
        L = lrow4[t];
    }

    __syncthreads();

    const int n = nh / H_DIM;
    const int y = nh % H_DIM;
    float* ob = out + ((size_t)(n * D_DIM + d0) * H_DIM + y) * W_DIM;

    if (t < W4) {
        const int x0 = 4 * t;                   // first x this thread owns
        const int c0 = PAD - d0 + x0;           // smem float index of R[x0 - d0]

        #pragma unroll
        for (int k = 0; k < D_CHUNK; ++k) {
            const int d   = d0 + k;
            const int s   = c0 - k;             // smem float index of R[x0 - d]
            const int b4  = s >> 2;
            const int off = (4 - (k & 3)) & 3;  // == s & 3, compile-time per k

            const float4 A = sr4[b4];
            float4 B = make_float4(0.f, 0.f, 0.f, 0.f);
            if (off) B = sr4[b4 + 1];

            float R0, R1, R2, R3;
            if (off == 0)      { R0 = A.x; R1 = A.y; R2 = A.z; R3 = A.w; }
            else if (off == 1) { R0 = A.y; R1 = A.z; R2 = A.w; R3 = B.x; }
            else if (off == 2) { R0 = A.z; R1 = A.w; R2 = B.x; R3 = B.y; }
            else               { R0 = A.w; R1 = B.x; R2 = B.y; R3 = B.z; }

            float4 v;
            v.x = (x0 + 0 >= d) ? fabsf(L.x - R0) : 0.f;
            v.y = (x0 + 1 >= d) ? fabsf(L.y - R1) : 0.f;
            v.z = (x0 + 2 >= d) ? fabsf(L.z - R2) : 0.f;
            v.w = (x0 + 3 >= d) ? fabsf(L.w - R3) : 0.f;

            stcs4((float4*)(ob + (size_t)k * (H_DIM * W_DIM)) + t, v);
        }
    }
}

extern "C" void kernel_launch(void* const* d_in, const int* in_sizes, int n_in,
                              void* d_out, int out_size)
{
    const float* image1 = (const float*)d_in[0];  // left
    const float* image2 = (const float*)d_in[1];  // right (shifted source)
    float* out = (float*)d_out;

    (void)in_sizes; (void)n_in; (void)out_size;

    dim3 grid(N_DIM * H_DIM, D_SPLIT);   // 768 x 16 = 12288 blocks
    dim3 block(THREADS);
    absdiff_costvol_kernel<<<grid, block>>>(image1, image2, out);
}

// round 4
// speedup vs baseline: 1.2099x; 1.0005x over previous
#include <cuda_runtime.h>
#include <cuda_bf16.h>

// AbsDiff cost volume:
//   out[n, d, y, x] = |image1[n,0,y,x] - image2[n,0,y,x-d]|  if x-d >= 0 else 0
// in [2,1,384,1248] fp32, out [2,128,384,1248] fp32. HBM-write-bound (~491MB).
// R4: kill per-d LDS. For the 8 unrolled d's, all shifted windows live inside
// a 12-float span -> load 3 float4 from smem ONCE, select in registers
// (compile-time offsets). L1 now serves ~only the STG.128 stream.

#define W_DIM    1248
#define H_DIM    384
#define N_DIM    2
#define D_DIM    128
#define W4       (W_DIM / 4)          // 312
#define THREADS  320                  // 10 warps; threads >= W4
#define D_SPLIT  16
#define D_CHUNK  (D_DIM / D_SPLIT)    // 8; d0 is a multiple of 8 (and of 4)
#define PAD      128                  // leading zeros: x-d never underflows

__device__ __forceinline__ void stcs4(float4* p, float4 v) {
    asm volatile("st.global.cs.v4.f32 [%0], {%1,%2,%3,%4};"
                 :: "l"(p), "f"(v.x), "f"(v.y), "f"(v.z), "f"(v.w) : "memory");
}

__global__ __launch_bounds__(THREADS, 6)
void absdiff_costvol_kernel(const float* __restrict__ left,
                            const float* __restrict__ right,
                            float* __restrict__ out)
{
    __shared__ float4 sr4[(PAD + W_DIM) / 4];   // 344 float4 = 5.5 KB

    const int nh = blockIdx.x;                  // n*H + y   (768)
    const int d0 = blockIdx.y * D_CHUNK;        // multiple of 8
    const int t  = threadIdx.x;

    const float4* rrow4 = (const float4*)(right + (size_t)nh * W_DIM);
    const float4* lrow4 = (const float4*)(left  + (size_t)nh * W_DIM);

    // Stage: zeros in the pad, right row after it.
    if (t < PAD / 4)
        sr4[t] = make_float4(0.f, 0.f, 0.f, 0.f);
    float4 L = make_float4(0.f, 0.f, 0.f, 0.f);
    if (t < W4) {
        sr4[PAD / 4 + t] = rrow4[t];
        L = lrow4[t];
    }

    __syncthreads();

    const int n = nh / H_DIM;
    const int y = nh % H_DIM;
    float* ob = out + ((size_t)(n * D_DIM + d0) * H_DIM + y) * W_DIM;

    if (t < W4) {
        const int x0 = 4 * t;                   // first x this thread owns
        const int c0 = PAD - d0 + x0;           // smem float idx of R[x0-d0]; %4==0
        const int b4 = c0 >> 2;                 // >= 2 always (c0 >= 8)

        // One-shot window load: floats [c0-8, c0+3] cover all 8 shifted reads.
        float w[12];
        {
            const float4 X = sr4[b4 - 2];
            const float4 Y = sr4[b4 - 1];
            const float4 Z = sr4[b4];
            w[0]=X.x; w[1]=X.y; w[2]=X.z;  w[3]=X.w;
            w[4]=Y.x; w[5]=Y.y; w[6]=Y.z;  w[7]=Y.w;
            w[8]=Z.x; w[9]=Z.y; w[10]=Z.z; w[11]=Z.w;
        }

        #pragma unroll
        for (int k = 0; k < D_CHUNK; ++k) {
            const int d  = d0 + k;
            const int j0 = 8 - k;               // window start inside w[], const

            float4 v;
            v.x = (x0 + 0 >= d) ? fabsf(L.x - w[j0 + 0]) : 0.f;
            v.y = (x0 + 1 >= d) ? fabsf(L.y - w[j0 + 1]) : 0.f;
            v.z = (x0 + 2 >= d) ? fabsf(L.z - w[j0 + 2]) : 0.f;
            v.w = (x0 + 3 >= d) ? fabsf(L.w - w[j0 + 3]) : 0.f;

            stcs4((float4*)(ob + (size_t)k * (H_DIM * W_DIM)) + t, v);
        }
    }
}

extern "C" void kernel_launch(void* const* d_in, const int* in_sizes, int n_in,
                              void* d_out, int out_size)
{
    const float* image1 = (const float*)d_in[0];  // left
    const float* image2 = (const float*)d_in[1];  // right (shifted source)
    float* out = (float*)d_out;

    (void)in_sizes; (void)n_in; (void)out_size;

    dim3 grid(N_DIM * H_DIM, D_SPLIT);   // 768 x 16 = 12288 blocks
    dim3 block(THREADS);
    absdiff_costvol_kernel<<<grid, block>>>(image1, image2, out);
}